// round 1
// baseline (speedup 1.0000x reference)
#include <cuda_runtime.h>
#include <cuda_bf16.h>
#include <math.h>

// ---------------------------------------------------------------------------
// MLA forward (fp32 baseline). B=2 S=2048 DIM=2048 H=16 QLR=1536 KVLR=512
// D_NOPE=128 D_ROPE=64 D_QK=192 D_V=128.
// Pipeline:
//   1. qa   = x @ wq_a                      [4096,1536]
//   2. kv   = x @ wkv_a                     [4096,576]
//   3. rmsnorm(qa) in place
//   4. kext = [rmsnorm(kv[:,:512])*w , rope(kv[:,512:])]   [4096,576]
//   5. q    = qa @ wq_b                     [4096,3072]
//   6. qext[:,512:576] = rope(q_pe)         per (m,h)
//   7. qext[:,0:512]   = q_nope @ Wuk^T     (batched over h, NT)
//   8. scores = qext @ kext^T * (mask)      batched over (b,h), causal tile skip
//   9. causal softmax (scale folded in), zero-fill up to 128-aligned bound
//  10. olat  = attn @ kext[:,0:512]         causal K-limit
//  11. ohead = olat @ Wuv^T                 batched over h
//  12. out   = ohead @ wo
// ---------------------------------------------------------------------------

#define BSZ    2
#define SEQ    2048
#define DMODEL 2048
#define NH     16
#define QLR    1536
#define KVLR   512
#define D_NOPE 128
#define D_ROPE 64
#define D_QK   192
#define D_V    128
#define MS     (BSZ*SEQ)          /* 4096 */
#define QDIM   (NH*D_QK)          /* 3072 */
#define KVD    (KVLR + D_ROPE)    /* 576  */
#define HDIM   (D_NOPE + D_V)     /* 256  */
#define EPSF   1e-6f

// ------------------------- scratch (device globals) ------------------------
__device__ float g_qa   [(size_t)MS * QLR];
__device__ float g_q    [(size_t)MS * QDIM];
__device__ float g_kv   [(size_t)MS * KVD];
__device__ float g_kext [(size_t)MS * KVD];
__device__ float g_qext [(size_t)MS * NH * KVD];
__device__ float g_scores[(size_t)BSZ * NH * SEQ * SEQ];
__device__ float g_olat [(size_t)BSZ * NH * SEQ * KVLR];
__device__ float g_ohead[(size_t)MS * DMODEL];

// ----------------------------- generic GEMM --------------------------------
// C[m,n] = sum_k A[m*lda_m + k] * B[k*ldb_k + n*ldb_n]
// Batched via blockIdx.z: z -> (zb = z/nInner, zh = z%nInner); per-operand
// offsets aSb/aSh etc. causal: 1 = skip C tiles fully above diagonal,
// 2 = limit K loop to m0+128 (A columns beyond are zero / never needed).
struct GemmP {
    const float* A; const float* B; float* C;
    int M, N, K;
    long long lda_m, ldb_k, ldb_n, ldc;
    long long aSb, aSh, bSb, bSh, cSb, cSh;
    int nInner;
    int causal;
};

__global__ __launch_bounds__(256, 2) void gemm_k(GemmP p) {
    __shared__ float As[16][132];
    __shared__ float Bs[16][132];

    const int m0 = blockIdx.y * 128;
    const int n0 = blockIdx.x * 128;
    if (p.causal == 1 && n0 >= m0 + 128) return;

    const int z  = blockIdx.z;
    const int zb = z / p.nInner;
    const int zh = z - zb * p.nInner;
    const float* A = p.A + zb * p.aSb + zh * p.aSh;
    const float* B = p.B + zb * p.bSb + zh * p.bSh;
    float*       C = p.C + zb * p.cSb + zh * p.cSh;

    int kEnd = p.K;
    if (p.causal == 2) { int km = m0 + 128; if (km < kEnd) kEnd = km; }

    const int tid = threadIdx.x;
    const int tx  = tid & 15;      // n micro-tile
    const int ty  = tid >> 4;      // m micro-tile

    float acc[8][8];
#pragma unroll
    for (int i = 0; i < 8; ++i)
#pragma unroll
        for (int j = 0; j < 8; ++j) acc[i][j] = 0.f;

    const bool bKfast = (p.ldb_n != 1);   // B is k-contiguous (NT layout)

    for (int k0 = 0; k0 < kEnd; k0 += 16) {
        // load A tile (k-contiguous in gmem)
#pragma unroll
        for (int i = 0; i < 8; ++i) {
            int idx = tid + i * 256;
            int mm = idx >> 4, kk = idx & 15;
            int gm = m0 + mm, gk = k0 + kk;
            float v = 0.f;
            if (gm < p.M && gk < p.K) v = A[(long long)gm * p.lda_m + gk];
            As[kk][mm] = v;
        }
        // load B tile
#pragma unroll
        for (int i = 0; i < 8; ++i) {
            int idx = tid + i * 256;
            int nn, kk;
            if (bKfast) { nn = idx >> 4;  kk = idx & 15; }
            else        { nn = idx & 127; kk = idx >> 7; }
            int gn = n0 + nn, gk = k0 + kk;
            float v = 0.f;
            if (gn < p.N && gk < p.K)
                v = B[(long long)gk * p.ldb_k + (long long)gn * p.ldb_n];
            Bs[kk][nn] = v;
        }
        __syncthreads();

#pragma unroll
        for (int kk = 0; kk < 16; ++kk) {
            float a[8], b[8];
#pragma unroll
            for (int i = 0; i < 8; ++i) a[i] = As[kk][ty * 8 + i];
#pragma unroll
            for (int j = 0; j < 8; ++j) b[j] = Bs[kk][tx * 8 + j];
#pragma unroll
            for (int i = 0; i < 8; ++i)
#pragma unroll
                for (int j = 0; j < 8; ++j)
                    acc[i][j] = fmaf(a[i], b[j], acc[i][j]);
        }
        __syncthreads();
    }

#pragma unroll
    for (int i = 0; i < 8; ++i) {
        int gm = m0 + ty * 8 + i;
        if (gm >= p.M) continue;
        float* crow = C + (long long)gm * p.ldc;
#pragma unroll
        for (int j = 0; j < 8; ++j) {
            int gn = n0 + tx * 8 + j;
            if (gn < p.N) crow[gn] = acc[i][j];
        }
    }
}

// ---------------------------- block reduction ------------------------------
__device__ __forceinline__ float blockReduce(float v, bool isMax) {
    __shared__ float sh[32];
    const int lane = threadIdx.x & 31, wid = threadIdx.x >> 5;
    __syncthreads();   // protect sh reuse across consecutive calls
#pragma unroll
    for (int o = 16; o > 0; o >>= 1) {
        float t = __shfl_down_sync(0xffffffffu, v, o);
        v = isMax ? fmaxf(v, t) : (v + t);
    }
    if (lane == 0) sh[wid] = v;
    __syncthreads();
    const int nw = blockDim.x >> 5;
    if (wid == 0) {
        v = (lane < nw) ? sh[lane] : (isMax ? -1e30f : 0.f);
#pragma unroll
        for (int o = 16; o > 0; o >>= 1) {
            float t = __shfl_down_sync(0xffffffffu, v, o);
            v = isMax ? fmaxf(v, t) : (v + t);
        }
        if (lane == 0) sh[0] = v;
    }
    __syncthreads();
    return sh[0];
}

// ------------------------------ aux kernels --------------------------------
__global__ void rmsnorm_rows_k(float* x, const float* __restrict__ w, int n) {
    long long base = (long long)blockIdx.x * n;
    float ss = 0.f;
    for (int i = threadIdx.x; i < n; i += blockDim.x) { float v = x[base + i]; ss += v * v; }
    ss = blockReduce(ss, false);
    float rn = rsqrtf(ss / (float)n + EPSF);
    for (int i = threadIdx.x; i < n; i += blockDim.x) x[base + i] = x[base + i] * rn * w[i];
}

__global__ void kv_process_k(const float* __restrict__ kv, float* __restrict__ kext,
                             const float* __restrict__ w, const float* __restrict__ freqs) {
    const int m = blockIdx.x;
    const int s = m & (SEQ - 1);
    const float* kr = kv   + (long long)m * KVD;
    float*       ke = kext + (long long)m * KVD;
    float ss = 0.f;
    for (int i = threadIdx.x; i < KVLR; i += blockDim.x) { float v = kr[i]; ss += v * v; }
    ss = blockReduce(ss, false);
    float rn = rsqrtf(ss / (float)KVLR + EPSF);
    for (int i = threadIdx.x; i < KVLR; i += blockDim.x) ke[i] = kr[i] * rn * w[i];
    if (threadIdx.x < 32) {
        const int i = threadIdx.x;
        float th = freqs[s * 32 + i];
        float c, sn; sincosf(th, &sn, &c);
        float x0 = kr[KVLR + 2 * i], x1 = kr[KVLR + 2 * i + 1];
        ke[KVLR + 2 * i]     = x0 * c - x1 * sn;
        ke[KVLR + 2 * i + 1] = x0 * sn + x1 * c;
    }
}

__global__ void rope_q_k(const float* __restrict__ q, float* __restrict__ qext,
                         const float* __restrict__ freqs) {
    const int m = blockIdx.x;
    const int s = m & (SEQ - 1);
    const int h = threadIdx.x >> 5;
    const int i = threadIdx.x & 31;
    float th = freqs[s * 32 + i];
    float c, sn; sincosf(th, &sn, &c);
    const float* qr = q + (long long)m * QDIM + h * D_QK + D_NOPE;
    float*       qe = qext + ((long long)m * NH + h) * KVD + KVLR;
    float x0 = qr[2 * i], x1 = qr[2 * i + 1];
    qe[2 * i]     = x0 * c - x1 * sn;
    qe[2 * i + 1] = x0 * sn + x1 * c;
}

__global__ void softmax_causal_k(float* scores, float scale) {
    const int s = blockIdx.x;
    long long base = ((long long)blockIdx.y * SEQ + s) * SEQ;
    float* r = scores + base;
    const int n = s + 1;
    float mx = -1e30f;
    for (int t = threadIdx.x; t < n; t += blockDim.x) mx = fmaxf(mx, r[t]);
    mx = blockReduce(mx, true);
    float sum = 0.f;
    for (int t = threadIdx.x; t < n; t += blockDim.x) {
        float e = __expf((r[t] - mx) * scale);
        sum += e;
        r[t] = e;
    }
    sum = blockReduce(sum, false);
    float inv = 1.f / sum;
    for (int t = threadIdx.x; t < n; t += blockDim.x) r[t] *= inv;
    // zero-fill masked region up to 128-aligned bound so attn@V K-limit is valid
    const int bound = ((s >> 7) + 1) << 7;
    for (int t = n + threadIdx.x; t < bound; t += blockDim.x) r[t] = 0.f;
}

// ------------------------------- host side ---------------------------------
static void launchGemm(const float* A, const float* B, float* C,
                       int M, int N, int K,
                       long long lda_m, long long ldb_k, long long ldb_n, long long ldc,
                       int nb, int nInner,
                       long long aSb, long long aSh,
                       long long bSb, long long bSh,
                       long long cSb, long long cSh,
                       int causal) {
    GemmP p;
    p.A = A; p.B = B; p.C = C;
    p.M = M; p.N = N; p.K = K;
    p.lda_m = lda_m; p.ldb_k = ldb_k; p.ldb_n = ldb_n; p.ldc = ldc;
    p.aSb = aSb; p.aSh = aSh; p.bSb = bSb; p.bSh = bSh; p.cSb = cSb; p.cSh = cSh;
    p.nInner = nInner; p.causal = causal;
    dim3 grid((N + 127) / 128, (M + 127) / 128, nb);
    gemm_k<<<grid, 256>>>(p);
}

extern "C" void kernel_launch(void* const* d_in, const int* in_sizes, int n_in,
                              void* d_out, int out_size) {
    const float* x         = (const float*)d_in[0];
    const float* freqs     = (const float*)d_in[1];
    /* d_in[2] = start_pos (always 0 for this problem) */
    const float* wq_a      = (const float*)d_in[3];
    const float* q_norm_w  = (const float*)d_in[4];
    const float* wq_b      = (const float*)d_in[5];
    const float* wkv_a     = (const float*)d_in[6];
    const float* kv_norm_w = (const float*)d_in[7];
    const float* wkv_b     = (const float*)d_in[8];
    const float* wo        = (const float*)d_in[9];
    float* out = (float*)d_out;

    float *qa, *q, *kv, *kext, *qext, *scores, *olat, *ohead;
    cudaGetSymbolAddress((void**)&qa,     g_qa);
    cudaGetSymbolAddress((void**)&q,      g_q);
    cudaGetSymbolAddress((void**)&kv,     g_kv);
    cudaGetSymbolAddress((void**)&kext,   g_kext);
    cudaGetSymbolAddress((void**)&qext,   g_qext);
    cudaGetSymbolAddress((void**)&scores, g_scores);
    cudaGetSymbolAddress((void**)&olat,   g_olat);
    cudaGetSymbolAddress((void**)&ohead,  g_ohead);

    const float scale = 1.0f / sqrtf((float)D_QK);

    // 1. qa = x @ wq_a
    launchGemm(x, wq_a, qa, MS, QLR, DMODEL,
               DMODEL, QLR, 1, QLR,
               1, 1, 0, 0, 0, 0, 0, 0, 0);
    // 2. kv = x @ wkv_a
    launchGemm(x, wkv_a, kv, MS, KVD, DMODEL,
               DMODEL, KVD, 1, KVD,
               1, 1, 0, 0, 0, 0, 0, 0, 0);
    // 3. rmsnorm(qa)
    rmsnorm_rows_k<<<MS, 256>>>(qa, q_norm_w, QLR);
    // 4. kext = [rmsnorm(kv latent), rope(k_pe)]
    kv_process_k<<<MS, 256>>>(kv, kext, kv_norm_w, freqs);
    // 5. q = qa @ wq_b
    launchGemm(qa, wq_b, q, MS, QDIM, QLR,
               QLR, QDIM, 1, QDIM,
               1, 1, 0, 0, 0, 0, 0, 0, 0);
    // 6. rope q_pe -> qext[:,512:576]
    rope_q_k<<<MS, NH * 32>>>(q, qext, freqs);
    // 7. qext[:,0:512] = q_nope @ wkv_b_nope^T  (batched over heads, B is NT)
    launchGemm(q, wkv_b, qext, MS, KVLR, D_NOPE,
               QDIM, 1, (long long)NH * HDIM, (long long)NH * KVD,
               NH, NH,
               0, D_QK,
               0, HDIM,
               0, KVD, 0);
    // 8. scores = qext @ kext^T  (batched over (b,h), causal tile skip)
    launchGemm(qext, kext, scores, SEQ, SEQ, KVD,
               (long long)NH * KVD, 1, KVD, SEQ,
               BSZ * NH, NH,
               (long long)SEQ * NH * KVD, KVD,
               (long long)SEQ * KVD, 0,
               (long long)NH * SEQ * SEQ, (long long)SEQ * SEQ,
               1);
    // 9. causal softmax (scale folded in)
    softmax_causal_k<<<dim3(SEQ, BSZ * NH), 256>>>(scores, scale);
    // 10. olat = attn @ kext[:,0:512]  (causal K-limit)
    launchGemm(scores, kext, olat, SEQ, KVLR, SEQ,
               SEQ, KVD, 1, KVLR,
               BSZ * NH, NH,
               (long long)NH * SEQ * SEQ, (long long)SEQ * SEQ,
               (long long)SEQ * KVD, 0,
               (long long)NH * SEQ * KVLR, (long long)SEQ * KVLR,
               2);
    // 11. ohead = olat @ wkv_b_v^T  (batched over (b,h); B base offset +D_NOPE)
    launchGemm(olat, wkv_b + D_NOPE, ohead, SEQ, D_V, KVLR,
               KVLR, (long long)NH * HDIM, 1, DMODEL,
               BSZ * NH, NH,
               (long long)NH * SEQ * KVLR, (long long)SEQ * KVLR,
               0, HDIM,
               (long long)SEQ * DMODEL, D_V,
               0);
    // 12. out = ohead @ wo
    launchGemm(ohead, wo, out, MS, DMODEL, DMODEL,
               DMODEL, DMODEL, 1, DMODEL,
               1, 1, 0, 0, 0, 0, 0, 0, 0);
}

// round 2
// speedup vs baseline: 3.0676x; 3.0676x over previous
#include <cuda_runtime.h>
#include <cuda_bf16.h>
#include <math.h>

// ---------------------------------------------------------------------------
// MLA forward, tf32 tensor-core GEMMs (mma.sync m16n8k8) + fp32 accumulate.
// B=2 S=2048 DIM=2048 H=16 QLR=1536 KVLR=512 D_NOPE=128 D_ROPE=64 D_QK=192 D_V=128
// ---------------------------------------------------------------------------

#define BSZ    2
#define SEQ    2048
#define DMODEL 2048
#define NH     16
#define QLR    1536
#define KVLR   512
#define D_NOPE 128
#define D_ROPE 64
#define D_QK   192
#define D_V    128
#define MS     (BSZ*SEQ)          /* 4096 */
#define QDIM   (NH*D_QK)          /* 3072 */
#define KVD    (KVLR + D_ROPE)    /* 576  */
#define HDIM   (D_NOPE + D_V)     /* 256  */
#define EPSF   1e-6f

// ------------------------- scratch (device globals) ------------------------
__device__ float g_qa   [(size_t)MS * QLR];
__device__ float g_q    [(size_t)MS * QDIM];
__device__ float g_kv   [(size_t)MS * KVD];
__device__ float g_kext [(size_t)MS * KVD];
__device__ float g_qext [(size_t)MS * NH * KVD];
__device__ float g_scores[(size_t)BSZ * NH * SEQ * SEQ];
__device__ float g_olat [(size_t)BSZ * NH * SEQ * KVLR];
__device__ float g_ohead[(size_t)MS * DMODEL];

// ----------------------------- GEMM plumbing -------------------------------
struct GemmP {
    const float* A; const float* B; float* C;
    int M, N, K;
    long long lda_m, ldb_k, ldb_n, ldc;
    long long aSb, aSh, bSb, bSh, cSb, cSh;
    int nInner;
    int causal;   // 1: skip C tiles above diagonal; 2: clamp K to m0+128
};

__device__ __forceinline__ unsigned f2tf32(float x) {
    unsigned u;
    asm("cvt.rna.tf32.f32 %0, %1;" : "=r"(u) : "f"(x));
    return u;
}
__device__ __forceinline__ uint4 cvt4(float4 v) {
    return make_uint4(f2tf32(v.x), f2tf32(v.y), f2tf32(v.z), f2tf32(v.w));
}
__device__ __forceinline__ void mma8(float* d, const unsigned* a, const unsigned* b) {
    asm volatile(
        "mma.sync.aligned.m16n8k8.row.col.f32.tf32.tf32.f32 "
        "{%0,%1,%2,%3}, {%4,%5,%6,%7}, {%8,%9}, {%0,%1,%2,%3};"
        : "+f"(d[0]), "+f"(d[1]), "+f"(d[2]), "+f"(d[3])
        : "r"(a[0]), "r"(a[1]), "r"(a[2]), "r"(a[3]),
          "r"(b[0]), "r"(b[1]));
}

// CTA tile 128x128, K-slab 16, 8 warps (2x4), warp tile 64x32.
// Smem strides: A=20 (conflict-free for frag rows), B=136 (conflict-free cols).
#define SA_STRIDE 20
#define SB_STRIDE 136

__global__ __launch_bounds__(256, 2) void gemm_tc(GemmP p) {
    __shared__ unsigned sA[128 * SA_STRIDE];
    __shared__ unsigned sB[16 * SB_STRIDE];

    const int m0 = blockIdx.y * 128;
    const int n0 = blockIdx.x * 128;
    if (p.causal == 1 && n0 >= m0 + 128) return;

    const int z  = blockIdx.z;
    const int zb = z / p.nInner;
    const int zh = z - zb * p.nInner;
    const float* A = p.A + zb * p.aSb + zh * p.aSh;
    const float* B = p.B + zb * p.bSb + zh * p.bSh;
    float*       C = p.C + zb * p.cSb + zh * p.cSh;

    int kEnd = p.K;
    if (p.causal == 2) { int km = m0 + 128; if (km < kEnd) kEnd = km; }

    const int tid  = threadIdx.x;
    const int lane = tid & 31;
    const int warp = tid >> 5;
    const int g    = lane >> 2;   // groupID
    const int c    = lane & 3;    // threadID_in_group
    const int wm   = warp >> 2;   // 0..1
    const int wn   = warp & 3;    // 0..3

    float acc[4][4][4];
#pragma unroll
    for (int i = 0; i < 4; ++i)
#pragma unroll
        for (int j = 0; j < 4; ++j)
#pragma unroll
            for (int l = 0; l < 4; ++l) acc[i][j][l] = 0.f;

    const bool bKfast = (p.ldb_n != 1);

    // ---- cooperative load addressing (per thread, k0 added later) ----
    // A: 128 rows x 16 k = 512 float4; thread t -> rows t>>2 and (t>>2)+64,
    //    k-offset (t&3)*4. All A operands are k-contiguous & 16B aligned;
    //    M is always a multiple of 128 -> no row bounds checks.
    const int aRow = tid >> 2;
    const int aK   = (tid & 3) * 4;
    const float* Ab0 = A + (long long)(m0 + aRow) * p.lda_m + aK;
    const float* Ab1 = Ab0 + 64 * p.lda_m;

    // B (bKfast, k-contiguous NT): thread -> n = t>>2 (+64), k-off (t&3)*4.
    //   (all NT uses have N a multiple of 128 -> no bounds checks)
    // B (NN, n-contiguous): thread -> k = t>>5 (+8), n-off (t&31)*4,
    //   bounds-checked against N (N=576 case).
    const float* Bb0;
    const float* Bb1;
    bool bOk = true;
    int  bN = 0, bKq4 = 0;
    if (bKfast) {
        bN   = tid >> 2;
        bKq4 = (tid & 3) * 4;
        Bb0 = B + (long long)(n0 + bN) * p.ldb_n + bKq4;
        Bb1 = Bb0 + 64 * p.ldb_n;
    } else {
        int bK = tid >> 5;
        bN = n0 + (tid & 31) * 4;
        bOk = (bN < p.N);
        Bb0 = B + (long long)bK * p.ldb_k + bN;
        Bb1 = Bb0 + 8 * p.ldb_k;
    }

    float4 ra0, ra1, rb0, rb1;
    const float4 z4 = make_float4(0.f, 0.f, 0.f, 0.f);

#define LOAD_TILE(K0)                                                          \
    do {                                                                       \
        ra0 = *(const float4*)(Ab0 + (K0));                                    \
        ra1 = *(const float4*)(Ab1 + (K0));                                    \
        if (bKfast) {                                                          \
            rb0 = *(const float4*)(Bb0 + (K0));                                \
            rb1 = *(const float4*)(Bb1 + (K0));                                \
        } else {                                                               \
            rb0 = bOk ? *(const float4*)(Bb0 + (long long)(K0) * p.ldb_k) : z4;\
            rb1 = bOk ? *(const float4*)(Bb1 + (long long)(K0) * p.ldb_k) : z4;\
        }                                                                      \
    } while (0)

#define STORE_TILE()                                                           \
    do {                                                                       \
        *(uint4*)(sA + aRow * SA_STRIDE + aK)        = cvt4(ra0);              \
        *(uint4*)(sA + (aRow + 64) * SA_STRIDE + aK) = cvt4(ra1);              \
        if (bKfast) {                                                          \
            sB[(bKq4 + 0) * SB_STRIDE + bN]      = f2tf32(rb0.x);              \
            sB[(bKq4 + 1) * SB_STRIDE + bN]      = f2tf32(rb0.y);              \
            sB[(bKq4 + 2) * SB_STRIDE + bN]      = f2tf32(rb0.z);              \
            sB[(bKq4 + 3) * SB_STRIDE + bN]      = f2tf32(rb0.w);              \
            sB[(bKq4 + 0) * SB_STRIDE + bN + 64] = f2tf32(rb1.x);              \
            sB[(bKq4 + 1) * SB_STRIDE + bN + 64] = f2tf32(rb1.y);              \
            sB[(bKq4 + 2) * SB_STRIDE + bN + 64] = f2tf32(rb1.z);              \
            sB[(bKq4 + 3) * SB_STRIDE + bN + 64] = f2tf32(rb1.w);              \
        } else {                                                               \
            int bk = tid >> 5, bn = (tid & 31) * 4;                            \
            *(uint4*)(sB + bk * SB_STRIDE + bn)       = cvt4(rb0);             \
            *(uint4*)(sB + (bk + 8) * SB_STRIDE + bn) = cvt4(rb1);             \
        }                                                                      \
    } while (0)

    LOAD_TILE(0);
    STORE_TILE();
    __syncthreads();

    for (int k0 = 0; k0 < kEnd; k0 += 16) {
        const bool nxt = (k0 + 16) < kEnd;
        if (nxt) LOAD_TILE(k0 + 16);

#pragma unroll
        for (int kk = 0; kk < 16; kk += 8) {
            unsigned af[4][4];
#pragma unroll
            for (int mi = 0; mi < 4; ++mi) {
                const unsigned* pa = sA + (wm * 64 + mi * 16 + g) * SA_STRIDE + kk + c;
                af[mi][0] = pa[0];
                af[mi][1] = pa[8 * SA_STRIDE];
                af[mi][2] = pa[4];
                af[mi][3] = pa[8 * SA_STRIDE + 4];
            }
            unsigned bf[4][2];
#pragma unroll
            for (int ni = 0; ni < 4; ++ni) {
                const unsigned* pb = sB + (kk + c) * SB_STRIDE + wn * 32 + ni * 8 + g;
                bf[ni][0] = pb[0];
                bf[ni][1] = pb[4 * SB_STRIDE];
            }
#pragma unroll
            for (int mi = 0; mi < 4; ++mi)
#pragma unroll
                for (int ni = 0; ni < 4; ++ni)
                    mma8(acc[mi][ni], af[mi], bf[ni]);
        }

        if (nxt) {
            __syncthreads();
            STORE_TILE();
            __syncthreads();
        }
    }

    // ---- epilogue ----
#pragma unroll
    for (int mi = 0; mi < 4; ++mi) {
        const int gm = m0 + wm * 64 + mi * 16 + g;
        float* r0 = C + (long long)gm * p.ldc;
        float* r1 = r0 + 8 * p.ldc;
#pragma unroll
        for (int ni = 0; ni < 4; ++ni) {
            const int gn = n0 + wn * 32 + ni * 8 + 2 * c;
            if (gn < p.N) {
                *(float2*)(r0 + gn) = make_float2(acc[mi][ni][0], acc[mi][ni][1]);
                *(float2*)(r1 + gn) = make_float2(acc[mi][ni][2], acc[mi][ni][3]);
            }
        }
    }
#undef LOAD_TILE
#undef STORE_TILE
}

// ---------------------------- block reduction ------------------------------
__device__ __forceinline__ float blockReduce(float v, bool isMax) {
    __shared__ float sh[32];
    const int lane = threadIdx.x & 31, wid = threadIdx.x >> 5;
    __syncthreads();
#pragma unroll
    for (int o = 16; o > 0; o >>= 1) {
        float t = __shfl_down_sync(0xffffffffu, v, o);
        v = isMax ? fmaxf(v, t) : (v + t);
    }
    if (lane == 0) sh[wid] = v;
    __syncthreads();
    const int nw = blockDim.x >> 5;
    if (wid == 0) {
        v = (lane < nw) ? sh[lane] : (isMax ? -1e30f : 0.f);
#pragma unroll
        for (int o = 16; o > 0; o >>= 1) {
            float t = __shfl_down_sync(0xffffffffu, v, o);
            v = isMax ? fmaxf(v, t) : (v + t);
        }
        if (lane == 0) sh[0] = v;
    }
    __syncthreads();
    return sh[0];
}

// ------------------------------ aux kernels --------------------------------
__global__ void rmsnorm_rows_k(float* x, const float* __restrict__ w, int n) {
    long long base = (long long)blockIdx.x * n;
    float ss = 0.f;
    for (int i = threadIdx.x; i < n; i += blockDim.x) { float v = x[base + i]; ss += v * v; }
    ss = blockReduce(ss, false);
    float rn = rsqrtf(ss / (float)n + EPSF);
    for (int i = threadIdx.x; i < n; i += blockDim.x) x[base + i] = x[base + i] * rn * w[i];
}

__global__ void kv_process_k(const float* __restrict__ kv, float* __restrict__ kext,
                             const float* __restrict__ w, const float* __restrict__ freqs) {
    const int m = blockIdx.x;
    const int s = m & (SEQ - 1);
    const float* kr = kv   + (long long)m * KVD;
    float*       ke = kext + (long long)m * KVD;
    float ss = 0.f;
    for (int i = threadIdx.x; i < KVLR; i += blockDim.x) { float v = kr[i]; ss += v * v; }
    ss = blockReduce(ss, false);
    float rn = rsqrtf(ss / (float)KVLR + EPSF);
    for (int i = threadIdx.x; i < KVLR; i += blockDim.x) ke[i] = kr[i] * rn * w[i];
    if (threadIdx.x < 32) {
        const int i = threadIdx.x;
        float th = freqs[s * 32 + i];
        float co, sn; sincosf(th, &sn, &co);
        float x0 = kr[KVLR + 2 * i], x1 = kr[KVLR + 2 * i + 1];
        ke[KVLR + 2 * i]     = x0 * co - x1 * sn;
        ke[KVLR + 2 * i + 1] = x0 * sn + x1 * co;
    }
}

__global__ void rope_q_k(const float* __restrict__ q, float* __restrict__ qext,
                         const float* __restrict__ freqs) {
    const int m = blockIdx.x;
    const int s = m & (SEQ - 1);
    const int h = threadIdx.x >> 5;
    const int i = threadIdx.x & 31;
    float th = freqs[s * 32 + i];
    float co, sn; sincosf(th, &sn, &co);
    const float* qr = q + (long long)m * QDIM + h * D_QK + D_NOPE;
    float*       qe = qext + ((long long)m * NH + h) * KVD + KVLR;
    float x0 = qr[2 * i], x1 = qr[2 * i + 1];
    qe[2 * i]     = x0 * co - x1 * sn;
    qe[2 * i + 1] = x0 * sn + x1 * co;
}

__global__ void softmax_causal_k(float* scores, float scale) {
    const int s = blockIdx.x;
    long long base = ((long long)blockIdx.y * SEQ + s) * SEQ;
    float* r = scores + base;
    const int n = s + 1;
    float mx = -1e30f;
    for (int t = threadIdx.x; t < n; t += blockDim.x) mx = fmaxf(mx, r[t]);
    mx = blockReduce(mx, true);
    float sum = 0.f;
    for (int t = threadIdx.x; t < n; t += blockDim.x) {
        float e = __expf((r[t] - mx) * scale);
        sum += e;
        r[t] = e;
    }
    sum = blockReduce(sum, false);
    float inv = 1.f / sum;
    for (int t = threadIdx.x; t < n; t += blockDim.x) r[t] *= inv;
    const int bound = ((s >> 7) + 1) << 7;
    for (int t = n + threadIdx.x; t < bound; t += blockDim.x) r[t] = 0.f;
}

// ------------------------------- host side ---------------------------------
static void launchGemm(const float* A, const float* B, float* C,
                       int M, int N, int K,
                       long long lda_m, long long ldb_k, long long ldb_n, long long ldc,
                       int nb, int nInner,
                       long long aSb, long long aSh,
                       long long bSb, long long bSh,
                       long long cSb, long long cSh,
                       int causal) {
    GemmP p;
    p.A = A; p.B = B; p.C = C;
    p.M = M; p.N = N; p.K = K;
    p.lda_m = lda_m; p.ldb_k = ldb_k; p.ldb_n = ldb_n; p.ldc = ldc;
    p.aSb = aSb; p.aSh = aSh; p.bSb = bSb; p.bSh = bSh; p.cSb = cSb; p.cSh = cSh;
    p.nInner = nInner; p.causal = causal;
    dim3 grid((N + 127) / 128, (M + 127) / 128, nb);
    gemm_tc<<<grid, 256>>>(p);
}

extern "C" void kernel_launch(void* const* d_in, const int* in_sizes, int n_in,
                              void* d_out, int out_size) {
    const float* x         = (const float*)d_in[0];
    const float* freqs     = (const float*)d_in[1];
    const float* wq_a      = (const float*)d_in[3];
    const float* q_norm_w  = (const float*)d_in[4];
    const float* wq_b      = (const float*)d_in[5];
    const float* wkv_a     = (const float*)d_in[6];
    const float* kv_norm_w = (const float*)d_in[7];
    const float* wkv_b     = (const float*)d_in[8];
    const float* wo        = (const float*)d_in[9];
    float* out = (float*)d_out;

    float *qa, *q, *kv, *kext, *qext, *scores, *olat, *ohead;
    cudaGetSymbolAddress((void**)&qa,     g_qa);
    cudaGetSymbolAddress((void**)&q,      g_q);
    cudaGetSymbolAddress((void**)&kv,     g_kv);
    cudaGetSymbolAddress((void**)&kext,   g_kext);
    cudaGetSymbolAddress((void**)&qext,   g_qext);
    cudaGetSymbolAddress((void**)&scores, g_scores);
    cudaGetSymbolAddress((void**)&olat,   g_olat);
    cudaGetSymbolAddress((void**)&ohead,  g_ohead);

    const float scale = 1.0f / sqrtf((float)D_QK);

    // 1. qa = x @ wq_a
    launchGemm(x, wq_a, qa, MS, QLR, DMODEL,
               DMODEL, QLR, 1, QLR,
               1, 1, 0, 0, 0, 0, 0, 0, 0);
    // 2. kv = x @ wkv_a
    launchGemm(x, wkv_a, kv, MS, KVD, DMODEL,
               DMODEL, KVD, 1, KVD,
               1, 1, 0, 0, 0, 0, 0, 0, 0);
    // 3. rmsnorm(qa)
    rmsnorm_rows_k<<<MS, 256>>>(qa, q_norm_w, QLR);
    // 4. kext = [rmsnorm(kv latent), rope(k_pe)]
    kv_process_k<<<MS, 256>>>(kv, kext, kv_norm_w, freqs);
    // 5. q = qa @ wq_b
    launchGemm(qa, wq_b, q, MS, QDIM, QLR,
               QLR, QDIM, 1, QDIM,
               1, 1, 0, 0, 0, 0, 0, 0, 0);
    // 6. rope q_pe -> qext[:,512:576]
    rope_q_k<<<MS, NH * 32>>>(q, qext, freqs);
    // 7. qext[:,0:512] = q_nope @ wkv_b_nope^T  (batched over heads, B is NT)
    launchGemm(q, wkv_b, qext, MS, KVLR, D_NOPE,
               QDIM, 1, (long long)NH * HDIM, (long long)NH * KVD,
               NH, NH,
               0, D_QK,
               0, HDIM,
               0, KVD, 0);
    // 8. scores = qext @ kext^T  (batched over (b,h), causal tile skip)
    launchGemm(qext, kext, scores, SEQ, SEQ, KVD,
               (long long)NH * KVD, 1, KVD, SEQ,
               BSZ * NH, NH,
               (long long)SEQ * NH * KVD, KVD,
               (long long)SEQ * KVD, 0,
               (long long)NH * SEQ * SEQ, (long long)SEQ * SEQ,
               1);
    // 9. causal softmax (scale folded in)
    softmax_causal_k<<<dim3(SEQ, BSZ * NH), 256>>>(scores, scale);
    // 10. olat = attn @ kext[:,0:512]  (causal K-limit)
    launchGemm(scores, kext, olat, SEQ, KVLR, SEQ,
               SEQ, KVD, 1, KVLR,
               BSZ * NH, NH,
               (long long)NH * SEQ * SEQ, (long long)SEQ * SEQ,
               (long long)SEQ * KVD, 0,
               (long long)NH * SEQ * KVLR, (long long)SEQ * KVLR,
               2);
    // 11. ohead = olat @ wkv_b_v^T
    launchGemm(olat, wkv_b + D_NOPE, ohead, SEQ, D_V, KVLR,
               KVLR, (long long)NH * HDIM, 1, DMODEL,
               BSZ * NH, NH,
               (long long)NH * SEQ * KVLR, (long long)SEQ * KVLR,
               0, HDIM,
               (long long)SEQ * DMODEL, D_V,
               0);
    // 12. out = ohead @ wo
    launchGemm(ohead, wo, out, MS, DMODEL, DMODEL,
               DMODEL, DMODEL, 1, DMODEL,
               1, 1, 0, 0, 0, 0, 0, 0, 0);
}

// round 3
// speedup vs baseline: 3.1233x; 1.0182x over previous
#include <cuda_runtime.h>
#include <cuda_bf16.h>
#include <math.h>
#include <stdint.h>

// ---------------------------------------------------------------------------
// MLA forward. All GEMMs: bf16x3 emulated-fp32 on packed operands
// (u32 = bf16_hi<<16 | bf16_lo), mma.sync m16n8k16, fp32 accumulate,
// cp.async 3-stage pipeline, XOR-swizzled smem, LDS.64 fragment loads.
// ---------------------------------------------------------------------------

#define BSZ    2
#define SEQ    2048
#define DMODEL 2048
#define NH     16
#define QLR    1536
#define KVLR   512
#define D_NOPE 128
#define D_ROPE 64
#define D_QK   192
#define D_V    128
#define MS     (BSZ*SEQ)          /* 4096 */
#define QDIM   (NH*D_QK)          /* 3072 */
#define KVD    (KVLR + D_ROPE)    /* 576  */
#define HDIM   (D_NOPE + D_V)     /* 256  */
#define EPSF   1e-6f

// ------------------------- scratch (device globals) ------------------------
__device__ uint32_t g_xp    [(size_t)MS * DMODEL];
__device__ uint32_t g_wqaT  [(size_t)QLR * DMODEL];
__device__ uint32_t g_wkvaT [(size_t)KVD * DMODEL];
__device__ uint32_t g_wqbT  [(size_t)QDIM * QLR];
__device__ uint32_t g_wkvbP [(size_t)KVLR * NH * HDIM];
__device__ uint32_t g_wkvbT [(size_t)NH * HDIM * KVLR];
__device__ uint32_t g_woT   [(size_t)DMODEL * DMODEL];
__device__ uint32_t g_qa    [(size_t)MS * QLR];
__device__ uint32_t g_q     [(size_t)MS * QDIM];
__device__ uint32_t g_kv    [(size_t)MS * KVD];
__device__ uint32_t g_kext  [(size_t)MS * KVD];
__device__ uint32_t g_kextT [(size_t)BSZ * KVLR * SEQ];
__device__ uint32_t g_qext  [(size_t)MS * NH * KVD];
__device__ float    g_scores[(size_t)BSZ * NH * SEQ * SEQ];
__device__ uint32_t g_olat  [(size_t)BSZ * NH * SEQ * KVLR];
__device__ uint32_t g_ohead [(size_t)MS * DMODEL];

// ------------------------------ pack helpers -------------------------------
__device__ __forceinline__ uint32_t packf(float x) {
    __nv_bfloat16 h = __float2bfloat16_rn(x);
    float hf = __bfloat162float(h);
    __nv_bfloat16 l = __float2bfloat16_rn(x - hf);
    return ((uint32_t)__bfloat16_as_ushort(h) << 16) | (uint32_t)__bfloat16_as_ushort(l);
}
__device__ __forceinline__ float upkf(uint32_t u) {
    return __uint_as_float(u & 0xFFFF0000u) + __uint_as_float(u << 16);
}
__device__ __forceinline__ uint32_t prmt(uint32_t a, uint32_t b, uint32_t sel) {
    uint32_t r;
    asm("prmt.b32 %0, %1, %2, %3;" : "=r"(r) : "r"(a), "r"(b), "r"(sel));
    return r;
}
#define PRMT_HI 0x7632u   /* (hi(a), hi(b)) as bf16x2 */
#define PRMT_LO 0x5410u   /* (lo(a), lo(b)) as bf16x2 */

__device__ __forceinline__ void mma_bf16(float* d, uint32_t a0, uint32_t a1,
                                         uint32_t a2, uint32_t a3,
                                         uint32_t b0, uint32_t b1) {
    asm volatile(
        "mma.sync.aligned.m16n8k16.row.col.f32.bf16.bf16.f32 "
        "{%0,%1,%2,%3}, {%4,%5,%6,%7}, {%8,%9}, {%0,%1,%2,%3};"
        : "+f"(d[0]), "+f"(d[1]), "+f"(d[2]), "+f"(d[3])
        : "r"(a0), "r"(a1), "r"(a2), "r"(a3), "r"(b0), "r"(b1));
}

__device__ __forceinline__ void cp16(unsigned smem, const void* g, int srcBytes) {
    asm volatile("cp.async.cg.shared.global [%0], [%1], 16, %2;"
                 :: "r"(smem), "l"(g), "r"(srcBytes));
}
__device__ __forceinline__ void cp_commit() { asm volatile("cp.async.commit_group;"); }
__device__ __forceinline__ void cp_wait1()  { asm volatile("cp.async.wait_group 1;"); }

// ----------------------------- GEMM (bf16x3) --------------------------------
// A: packed u32, row-major M x K (row stride lda).  B: packed u32, row-major
// N x K (row stride ldb) -- i.e. C = A * B^T.  C row stride ldc.
// outMode: 0 = fp32, 1 = packed u32.
// causal: 1 = skip C tiles above diagonal; 2 = clamp K to m0+128.
struct GemmP {
    const uint32_t* A; const uint32_t* B; void* C;
    int M, N, K;
    long long lda, ldb, ldc;
    long long aSb, aSh, bSb, bSh, cSb, cSh;
    int nInner;
    int causal;
    int outMode;
};

#define STAGES 3
// smem stage layout: A tile 128x16 u32 (8KB, swizzled) then B tile (8KB).
// swizzle: 16B chunk q of row r stored at q ^ (((r>>1)&1)<<1).

__device__ __forceinline__ uint2 ldpair(const uint32_t* base, int row, int k) {
    int q = (k >> 2) ^ (((row >> 1) & 1) << 1);
    return *(const uint2*)(base + row * 16 + q * 4 + (k & 3));
}

__global__ __launch_bounds__(256, 2) void gemm_bf16x3(GemmP p) {
    __shared__ uint32_t sm[STAGES][2][128 * 16];   // 48KB

    const int m0 = blockIdx.y * 128;
    const int n0 = blockIdx.x * 128;
    if (p.causal == 1 && n0 >= m0 + 128) return;

    const int z  = blockIdx.z;
    const int zb = z / p.nInner;
    const int zh = z - zb * p.nInner;
    const uint32_t* A = p.A + zb * p.aSb + zh * p.aSh;
    const uint32_t* B = p.B + zb * p.bSb + zh * p.bSh;

    int kEnd = p.K;
    if (p.causal == 2) { int km = m0 + 128; if (km < kEnd) kEnd = km; }
    const int nSlab = kEnd >> 4;

    const int tid  = threadIdx.x;
    const int lane = tid & 31;
    const int warp = tid >> 5;
    const int g    = lane >> 2;
    const int c    = lane & 3;
    const int wm   = warp >> 2;    // 0..1
    const int wn   = warp & 3;     // 0..3

    // producer addressing: thread -> (row, 2 chunks)
    const int prow = tid >> 1;
    const int pq   = (tid & 1) << 1;
    const int swp  = ((prow >> 1) & 1) << 1;
    const unsigned dOff = (unsigned)(prow * 64 + ((pq ^ swp) * 16));
    unsigned smBase = (unsigned)__cvta_generic_to_shared(&sm[0][0][0]);

    const uint32_t* Agp = A + (size_t)(m0 + prow) * p.lda + pq * 4;
    const bool bok = (n0 + prow) < p.N;
    const uint32_t* Bgp = B + (size_t)(bok ? (n0 + prow) : 0) * p.ldb + pq * 4;
    const int bsz = bok ? 16 : 0;

#define ISSUE(SLAB)                                                            \
    do {                                                                       \
        unsigned sb = smBase + (unsigned)(((SLAB) % STAGES) * 16384);          \
        const uint32_t* ag = Agp + (SLAB) * 16;                                \
        const uint32_t* bg = Bgp + (SLAB) * 16;                                \
        cp16(sb + dOff,        ag,     16);                                    \
        cp16(sb + dOff + 16,   ag + 4, 16);                                    \
        cp16(sb + 8192 + dOff,      bg,     bsz);                              \
        cp16(sb + 8192 + dOff + 16, bg + 4, bsz);                              \
    } while (0)

    float acc[4][4][4];
#pragma unroll
    for (int i = 0; i < 4; ++i)
#pragma unroll
        for (int j = 0; j < 4; ++j)
#pragma unroll
            for (int l = 0; l < 4; ++l) acc[i][j][l] = 0.f;

    // prologue: prefetch first STAGES-1 slabs
    {
        int np = nSlab < (STAGES - 1) ? nSlab : (STAGES - 1);
        for (int s = 0; s < np; ++s) { ISSUE(s); cp_commit(); }
        for (int s = np; s < STAGES - 1; ++s) cp_commit();
    }

    for (int it = 0; it < nSlab; ++it) {
        cp_wait1();
        __syncthreads();

        const uint32_t* sa = &sm[it % STAGES][0][0];
        const uint32_t* sb = &sm[it % STAGES][1][0];

        uint32_t Ah[4][4], Al[4][4];
#pragma unroll
        for (int mi = 0; mi < 4; ++mi) {
            const int r = wm * 64 + mi * 16 + g;
            uint2 w0 = ldpair(sa, r,     2 * c);
            uint2 w1 = ldpair(sa, r + 8, 2 * c);
            uint2 w2 = ldpair(sa, r,     2 * c + 8);
            uint2 w3 = ldpair(sa, r + 8, 2 * c + 8);
            Ah[mi][0] = prmt(w0.x, w0.y, PRMT_HI); Al[mi][0] = prmt(w0.x, w0.y, PRMT_LO);
            Ah[mi][1] = prmt(w1.x, w1.y, PRMT_HI); Al[mi][1] = prmt(w1.x, w1.y, PRMT_LO);
            Ah[mi][2] = prmt(w2.x, w2.y, PRMT_HI); Al[mi][2] = prmt(w2.x, w2.y, PRMT_LO);
            Ah[mi][3] = prmt(w3.x, w3.y, PRMT_HI); Al[mi][3] = prmt(w3.x, w3.y, PRMT_LO);
        }
#pragma unroll
        for (int ni = 0; ni < 4; ++ni) {
            const int n = wn * 32 + ni * 8 + g;
            uint2 v0 = ldpair(sb, n, 2 * c);
            uint2 v1 = ldpair(sb, n, 2 * c + 8);
            uint32_t bh0 = prmt(v0.x, v0.y, PRMT_HI), bl0 = prmt(v0.x, v0.y, PRMT_LO);
            uint32_t bh1 = prmt(v1.x, v1.y, PRMT_HI), bl1 = prmt(v1.x, v1.y, PRMT_LO);
#pragma unroll
            for (int mi = 0; mi < 4; ++mi) {
                mma_bf16(acc[mi][ni], Ah[mi][0], Ah[mi][1], Ah[mi][2], Ah[mi][3], bh0, bh1);
                mma_bf16(acc[mi][ni], Ah[mi][0], Ah[mi][1], Ah[mi][2], Ah[mi][3], bl0, bl1);
                mma_bf16(acc[mi][ni], Al[mi][0], Al[mi][1], Al[mi][2], Al[mi][3], bh0, bh1);
            }
        }

        if (it + STAGES - 1 < nSlab) ISSUE(it + STAGES - 1);
        cp_commit();
    }
#undef ISSUE

    // ---- epilogue ----
    if (p.outMode == 0) {
        float* C = (float*)p.C + zb * p.cSb + zh * p.cSh;
#pragma unroll
        for (int mi = 0; mi < 4; ++mi) {
            const int gm = m0 + wm * 64 + mi * 16 + g;
            float* r0 = C + (long long)gm * p.ldc;
            float* r1 = r0 + 8 * p.ldc;
#pragma unroll
            for (int ni = 0; ni < 4; ++ni) {
                const int gn = n0 + wn * 32 + ni * 8 + 2 * c;
                if (gn < p.N) {
                    *(float2*)(r0 + gn) = make_float2(acc[mi][ni][0], acc[mi][ni][1]);
                    *(float2*)(r1 + gn) = make_float2(acc[mi][ni][2], acc[mi][ni][3]);
                }
            }
        }
    } else {
        uint32_t* C = (uint32_t*)p.C + zb * p.cSb + zh * p.cSh;
#pragma unroll
        for (int mi = 0; mi < 4; ++mi) {
            const int gm = m0 + wm * 64 + mi * 16 + g;
            uint32_t* r0 = C + (long long)gm * p.ldc;
            uint32_t* r1 = r0 + 8 * p.ldc;
#pragma unroll
            for (int ni = 0; ni < 4; ++ni) {
                const int gn = n0 + wn * 32 + ni * 8 + 2 * c;
                if (gn < p.N) {
                    *(uint2*)(r0 + gn) = make_uint2(packf(acc[mi][ni][0]), packf(acc[mi][ni][1]));
                    *(uint2*)(r1 + gn) = make_uint2(packf(acc[mi][ni][2]), packf(acc[mi][ni][3]));
                }
            }
        }
    }
}

// ---------------------------- block reduction ------------------------------
__device__ __forceinline__ float blockReduce(float v, bool isMax) {
    __shared__ float sh[32];
    const int lane = threadIdx.x & 31, wid = threadIdx.x >> 5;
    __syncthreads();
#pragma unroll
    for (int o = 16; o > 0; o >>= 1) {
        float t = __shfl_down_sync(0xffffffffu, v, o);
        v = isMax ? fmaxf(v, t) : (v + t);
    }
    if (lane == 0) sh[wid] = v;
    __syncthreads();
    const int nw = blockDim.x >> 5;
    if (wid == 0) {
        v = (lane < nw) ? sh[lane] : (isMax ? -1e30f : 0.f);
#pragma unroll
        for (int o = 16; o > 0; o >>= 1) {
            float t = __shfl_down_sync(0xffffffffu, v, o);
            v = isMax ? fmaxf(v, t) : (v + t);
        }
        if (lane == 0) sh[0] = v;
    }
    __syncthreads();
    return sh[0];
}

// ------------------------------ aux kernels --------------------------------
__global__ void pack_k(const float* __restrict__ in, uint32_t* __restrict__ out, int n) {
    for (int i = blockIdx.x * blockDim.x + threadIdx.x; i < n; i += gridDim.x * blockDim.x)
        out[i] = packf(in[i]);
}

// in fp32 [R][C] -> out packed [C][R]
__global__ void packT_k(const float* __restrict__ in, uint32_t* __restrict__ out,
                        int R, int C) {
    __shared__ float t[32][33];
    const int c0 = blockIdx.x * 32, r0 = blockIdx.y * 32;
#pragma unroll
    for (int i = threadIdx.y; i < 32; i += 8)
        t[i][threadIdx.x] = in[(long long)(r0 + i) * C + c0 + threadIdx.x];
    __syncthreads();
#pragma unroll
    for (int i = threadIdx.y; i < 32; i += 8)
        out[(long long)(c0 + i) * R + r0 + threadIdx.x] = packf(t[threadIdx.x][i]);
}

__global__ void rmsnorm_rows_k(uint32_t* x, const float* __restrict__ w, int n) {
    long long base = (long long)blockIdx.x * n;
    float ss = 0.f;
    for (int i = threadIdx.x; i < n; i += blockDim.x) { float v = upkf(x[base + i]); ss += v * v; }
    ss = blockReduce(ss, false);
    float rn = rsqrtf(ss / (float)n + EPSF);
    for (int i = threadIdx.x; i < n; i += blockDim.x)
        x[base + i] = packf(upkf(x[base + i]) * rn * w[i]);
}

__global__ void kv_process_k(const uint32_t* __restrict__ kv, uint32_t* __restrict__ kext,
                             uint32_t* __restrict__ kextT,
                             const float* __restrict__ w, const float* __restrict__ freqs) {
    const int m = blockIdx.x;
    const int s = m & (SEQ - 1);
    const int b = m >> 11;
    const uint32_t* kr = kv   + (long long)m * KVD;
    uint32_t*       ke = kext + (long long)m * KVD;
    float ss = 0.f;
    for (int i = threadIdx.x; i < KVLR; i += blockDim.x) { float v = upkf(kr[i]); ss += v * v; }
    ss = blockReduce(ss, false);
    float rn = rsqrtf(ss / (float)KVLR + EPSF);
    for (int i = threadIdx.x; i < KVLR; i += blockDim.x) {
        uint32_t pv = packf(upkf(kr[i]) * rn * w[i]);
        ke[i] = pv;
        kextT[(long long)b * KVLR * SEQ + (long long)i * SEQ + s] = pv;
    }
    if (threadIdx.x < 32) {
        const int i = threadIdx.x;
        float th = freqs[s * 32 + i];
        float co, sn; sincosf(th, &sn, &co);
        float x0 = upkf(kr[KVLR + 2 * i]), x1 = upkf(kr[KVLR + 2 * i + 1]);
        ke[KVLR + 2 * i]     = packf(x0 * co - x1 * sn);
        ke[KVLR + 2 * i + 1] = packf(x0 * sn + x1 * co);
    }
}

__global__ void rope_q_k(const uint32_t* __restrict__ q, uint32_t* __restrict__ qext,
                         const float* __restrict__ freqs) {
    const int m = blockIdx.x;
    const int s = m & (SEQ - 1);
    const int h = threadIdx.x >> 5;
    const int i = threadIdx.x & 31;
    float th = freqs[s * 32 + i];
    float co, sn; sincosf(th, &sn, &co);
    const uint32_t* qr = q + (long long)m * QDIM + h * D_QK + D_NOPE;
    uint32_t*       qe = qext + ((long long)m * NH + h) * KVD + KVLR;
    float x0 = upkf(qr[2 * i]), x1 = upkf(qr[2 * i + 1]);
    qe[2 * i]     = packf(x0 * co - x1 * sn);
    qe[2 * i + 1] = packf(x0 * sn + x1 * co);
}

// softmax over fp32 scores row, writes PACKED attn in place (u32 alias).
__global__ void softmax_causal_k(float* scores, float scale) {
    const int s = blockIdx.x;
    long long base = ((long long)blockIdx.y * SEQ + s) * SEQ;
    float* r = scores + base;
    uint32_t* u = (uint32_t*)r;
    const int n = s + 1;
    float mx = -1e30f;
    for (int t = threadIdx.x; t < n; t += blockDim.x) mx = fmaxf(mx, r[t]);
    mx = blockReduce(mx, true);
    float sum = 0.f;
    for (int t = threadIdx.x; t < n; t += blockDim.x) {
        float e = __expf((r[t] - mx) * scale);
        sum += e;
        r[t] = e;
    }
    sum = blockReduce(sum, false);
    float inv = 1.f / sum;
    for (int t = threadIdx.x; t < n; t += blockDim.x) u[t] = packf(r[t] * inv);
    const int bound = ((s >> 7) + 1) << 7;
    for (int t = n + threadIdx.x; t < bound; t += blockDim.x) u[t] = 0u;
}

// ------------------------------- host side ---------------------------------
static void launchGemm(const uint32_t* A, const uint32_t* B, void* C,
                       int M, int N, int K,
                       long long lda, long long ldb, long long ldc,
                       int nb, int nInner,
                       long long aSb, long long aSh,
                       long long bSb, long long bSh,
                       long long cSb, long long cSh,
                       int causal, int outMode) {
    GemmP p;
    p.A = A; p.B = B; p.C = C;
    p.M = M; p.N = N; p.K = K;
    p.lda = lda; p.ldb = ldb; p.ldc = ldc;
    p.aSb = aSb; p.aSh = aSh; p.bSb = bSb; p.bSh = bSh; p.cSb = cSb; p.cSh = cSh;
    p.nInner = nInner; p.causal = causal; p.outMode = outMode;
    dim3 grid((N + 127) / 128, (M + 127) / 128, nb);
    gemm_bf16x3<<<grid, 256>>>(p);
}

extern "C" void kernel_launch(void* const* d_in, const int* in_sizes, int n_in,
                              void* d_out, int out_size) {
    const float* x         = (const float*)d_in[0];
    const float* freqs     = (const float*)d_in[1];
    const float* wq_a      = (const float*)d_in[3];
    const float* q_norm_w  = (const float*)d_in[4];
    const float* wq_b      = (const float*)d_in[5];
    const float* wkv_a     = (const float*)d_in[6];
    const float* kv_norm_w = (const float*)d_in[7];
    const float* wkv_b     = (const float*)d_in[8];
    const float* wo        = (const float*)d_in[9];
    float* out = (float*)d_out;

    uint32_t *xp, *wqaT, *wkvaT, *wqbT, *wkvbP, *wkvbT, *woT;
    uint32_t *qa, *q, *kv, *kext, *kextT, *qext, *olat, *ohead;
    float* scores;
    cudaGetSymbolAddress((void**)&xp,     g_xp);
    cudaGetSymbolAddress((void**)&wqaT,   g_wqaT);
    cudaGetSymbolAddress((void**)&wkvaT,  g_wkvaT);
    cudaGetSymbolAddress((void**)&wqbT,   g_wqbT);
    cudaGetSymbolAddress((void**)&wkvbP,  g_wkvbP);
    cudaGetSymbolAddress((void**)&wkvbT,  g_wkvbT);
    cudaGetSymbolAddress((void**)&woT,    g_woT);
    cudaGetSymbolAddress((void**)&qa,     g_qa);
    cudaGetSymbolAddress((void**)&q,      g_q);
    cudaGetSymbolAddress((void**)&kv,     g_kv);
    cudaGetSymbolAddress((void**)&kext,   g_kext);
    cudaGetSymbolAddress((void**)&kextT,  g_kextT);
    cudaGetSymbolAddress((void**)&qext,   g_qext);
    cudaGetSymbolAddress((void**)&scores, g_scores);
    cudaGetSymbolAddress((void**)&olat,   g_olat);
    cudaGetSymbolAddress((void**)&ohead,  g_ohead);

    const float scale = 1.0f / sqrtf((float)D_QK);

    // ---- pack / transpose-pack inputs ----
    pack_k<<<512, 256>>>(x, xp, MS * DMODEL);
    pack_k<<<256, 256>>>(wkv_b, wkvbP, KVLR * NH * HDIM);
    packT_k<<<dim3(QLR / 32, DMODEL / 32), dim3(32, 8)>>>(wq_a, wqaT, DMODEL, QLR);
    packT_k<<<dim3(KVD / 32, DMODEL / 32), dim3(32, 8)>>>(wkv_a, wkvaT, DMODEL, KVD);
    packT_k<<<dim3(QDIM / 32, QLR / 32), dim3(32, 8)>>>(wq_b, wqbT, QLR, QDIM);
    packT_k<<<dim3((NH * HDIM) / 32, KVLR / 32), dim3(32, 8)>>>(wkv_b, wkvbT, KVLR, NH * HDIM);
    packT_k<<<dim3(DMODEL / 32, DMODEL / 32), dim3(32, 8)>>>(wo, woT, DMODEL, DMODEL);

    // 1. qa = x @ wq_a          (B = wqaT [QLR][DMODEL])
    launchGemm(xp, wqaT, qa, MS, QLR, DMODEL,
               DMODEL, DMODEL, QLR,
               1, 1, 0, 0, 0, 0, 0, 0, 0, 1);
    // 2. kv = x @ wkv_a         (B = wkvaT [576][2048], N=576 OOB-guarded)
    launchGemm(xp, wkvaT, kv, MS, KVD, DMODEL,
               DMODEL, DMODEL, KVD,
               1, 1, 0, 0, 0, 0, 0, 0, 0, 1);
    // 3. rmsnorm(qa) in place (packed)
    rmsnorm_rows_k<<<MS, 256>>>(qa, q_norm_w, QLR);
    // 4. kext (+kextT)
    kv_process_k<<<MS, 256>>>(kv, kext, kextT, kv_norm_w, freqs);
    // 5. q = qa @ wq_b
    launchGemm(qa, wqbT, q, MS, QDIM, QLR,
               QLR, QLR, QDIM,
               1, 1, 0, 0, 0, 0, 0, 0, 0, 1);
    // 6. rope q_pe -> qext[:,512:576]
    rope_q_k<<<MS, NH * 32>>>(q, qext, freqs);
    // 7. qext[:,0:512] = q_nope @ wkv_b_nope^T  (B rows = c, k-contig)
    launchGemm(q, wkvbP, qext, MS, KVLR, D_NOPE,
               QDIM, NH * HDIM, (long long)NH * KVD,
               NH, NH,
               0, D_QK,
               0, HDIM,
               0, KVD, 0, 1);
    // 8. scores = qext @ kext^T  (fp32 out, causal tile skip)
    launchGemm(qext, kext, scores, SEQ, SEQ, KVD,
               (long long)NH * KVD, KVD, SEQ,
               BSZ * NH, NH,
               (long long)SEQ * NH * KVD, KVD,
               (long long)SEQ * KVD, 0,
               (long long)NH * SEQ * SEQ, (long long)SEQ * SEQ,
               1, 0);
    // 9. softmax -> packed attn in place
    softmax_causal_k<<<dim3(SEQ, BSZ * NH), 256>>>(scores, scale);
    // 10. olat = attn @ kv_cache   (B = kextT [b][c][t], causal K-limit)
    launchGemm((const uint32_t*)scores, kextT, olat, SEQ, KVLR, SEQ,
               SEQ, SEQ, KVLR,
               BSZ * NH, NH,
               (long long)NH * SEQ * SEQ, (long long)SEQ * SEQ,
               (long long)KVLR * SEQ, 0,
               (long long)NH * SEQ * KVLR, (long long)SEQ * KVLR,
               2, 1);
    // 11. ohead = olat @ wkv_b_v^T (B = wkvbT rows h*HDIM+128+n, k-contig)
    launchGemm(olat, wkvbT + (long long)D_NOPE * KVLR, ohead, SEQ, D_V, KVLR,
               KVLR, KVLR, DMODEL,
               BSZ * NH, NH,
               (long long)NH * SEQ * KVLR, (long long)SEQ * KVLR,
               0, (long long)HDIM * KVLR,
               (long long)SEQ * DMODEL, D_V,
               0, 1);
    // 12. out = ohead @ wo  (fp32 out)
    launchGemm(ohead, woT, out, MS, DMODEL, DMODEL,
               DMODEL, DMODEL, DMODEL,
               1, 1, 0, 0, 0, 0, 0, 0, 0, 0);
}

// round 4
// speedup vs baseline: 3.1294x; 1.0019x over previous
#include <cuda_runtime.h>
#include <cuda_bf16.h>
#include <math.h>
#include <stdint.h>

// ---------------------------------------------------------------------------
// MLA forward. All GEMMs: bf16x3 emulated-fp32 on packed operands
// (u32 = bf16_hi<<16 | bf16_lo), mma.sync m16n8k16, fp32 accumulate,
// cp.async 3-stage pipeline, XOR-swizzled smem, LDS.64 fragment loads.
// ---------------------------------------------------------------------------

#define BSZ    2
#define SEQ    2048
#define DMODEL 2048
#define NH     16
#define QLR    1536
#define KVLR   512
#define D_NOPE 128
#define D_ROPE 64
#define D_QK   192
#define D_V    128
#define MS     (BSZ*SEQ)          /* 4096 */
#define QDIM   (NH*D_QK)          /* 3072 */
#define KVD    (KVLR + D_ROPE)    /* 576  */
#define HDIM   (D_NOPE + D_V)     /* 256  */
#define EPSF   1e-6f

// ------------------------- scratch (device globals) ------------------------
__device__ uint32_t g_xp    [(size_t)MS * DMODEL];
__device__ uint32_t g_wqaT  [(size_t)QLR * DMODEL];
__device__ uint32_t g_wkvaT [(size_t)KVD * DMODEL];
__device__ uint32_t g_wqbT  [(size_t)QDIM * QLR];
__device__ uint32_t g_wkvbP [(size_t)KVLR * NH * HDIM];
__device__ uint32_t g_wkvbT [(size_t)NH * HDIM * KVLR];
__device__ uint32_t g_woT   [(size_t)DMODEL * DMODEL];
__device__ uint32_t g_qa    [(size_t)MS * QLR];
__device__ uint32_t g_q     [(size_t)MS * QDIM];
__device__ uint32_t g_kv    [(size_t)MS * KVD];
__device__ uint32_t g_kext  [(size_t)MS * KVD];
__device__ uint32_t g_kextT [(size_t)BSZ * KVLR * SEQ];
__device__ uint32_t g_qext  [(size_t)MS * NH * KVD];
__device__ float    g_scores[(size_t)BSZ * NH * SEQ * SEQ];
__device__ uint32_t g_olat  [(size_t)BSZ * NH * SEQ * KVLR];
__device__ uint32_t g_ohead [(size_t)MS * DMODEL];

// ------------------------------ pack helpers -------------------------------
__device__ __forceinline__ uint32_t packf(float x) {
    __nv_bfloat16 h = __float2bfloat16_rn(x);
    float hf = __bfloat162float(h);
    __nv_bfloat16 l = __float2bfloat16_rn(x - hf);
    return ((uint32_t)__bfloat16_as_ushort(h) << 16) | (uint32_t)__bfloat16_as_ushort(l);
}
__device__ __forceinline__ float upkf(uint32_t u) {
    return __uint_as_float(u & 0xFFFF0000u) + __uint_as_float(u << 16);
}
__device__ __forceinline__ uint32_t prmt(uint32_t a, uint32_t b, uint32_t sel) {
    uint32_t r;
    asm("prmt.b32 %0, %1, %2, %3;" : "=r"(r) : "r"(a), "r"(b), "r"(sel));
    return r;
}
#define PRMT_HI 0x7632u   /* (hi(a), hi(b)) as bf16x2 */
#define PRMT_LO 0x5410u   /* (lo(a), lo(b)) as bf16x2 */

__device__ __forceinline__ void mma_bf16(float* d, uint32_t a0, uint32_t a1,
                                         uint32_t a2, uint32_t a3,
                                         uint32_t b0, uint32_t b1) {
    asm volatile(
        "mma.sync.aligned.m16n8k16.row.col.f32.bf16.bf16.f32 "
        "{%0,%1,%2,%3}, {%4,%5,%6,%7}, {%8,%9}, {%0,%1,%2,%3};"
        : "+f"(d[0]), "+f"(d[1]), "+f"(d[2]), "+f"(d[3])
        : "r"(a0), "r"(a1), "r"(a2), "r"(a3), "r"(b0), "r"(b1));
}

__device__ __forceinline__ void cp16(unsigned smem, const void* g, int srcBytes) {
    asm volatile("cp.async.cg.shared.global [%0], [%1], 16, %2;"
                 :: "r"(smem), "l"(g), "r"(srcBytes));
}
__device__ __forceinline__ void cp_commit() { asm volatile("cp.async.commit_group;"); }
__device__ __forceinline__ void cp_wait1()  { asm volatile("cp.async.wait_group 1;"); }

// ----------------------------- GEMM (bf16x3) --------------------------------
// A: packed u32, row-major M x K (row stride lda).  B: packed u32, row-major
// N x K (row stride ldb) -- i.e. C = A * B^T.  C row stride ldc.
// outMode: 0 = fp32, 1 = packed u32.
// causal: 1 = skip C tiles above diagonal; 2 = clamp K to m0+128.
struct GemmP {
    const uint32_t* A; const uint32_t* B; void* C;
    int M, N, K;
    long long lda, ldb, ldc;
    long long aSb, aSh, bSb, bSh, cSb, cSh;
    int nInner;
    int causal;
    int outMode;
};

#define STAGES 3
// smem stage layout: A tile 128x16 u32 (8KB, swizzled) then B tile (8KB).
// swizzle: 16B chunk q of row r stored at q ^ (((r>>1)&1)<<1).

__device__ __forceinline__ uint2 ldpair(const uint32_t* base, int row, int k) {
    int q = (k >> 2) ^ (((row >> 1) & 1) << 1);
    return *(const uint2*)(base + row * 16 + q * 4 + (k & 3));
}

__global__ __launch_bounds__(256, 2) void gemm_bf16x3(GemmP p) {
    __shared__ uint32_t sm[STAGES][2][128 * 16];   // 48KB

    const int m0 = blockIdx.y * 128;
    const int n0 = blockIdx.x * 128;
    if (p.causal == 1 && n0 >= m0 + 128) return;

    const int z  = blockIdx.z;
    const int zb = z / p.nInner;
    const int zh = z - zb * p.nInner;
    const uint32_t* A = p.A + zb * p.aSb + zh * p.aSh;
    const uint32_t* B = p.B + zb * p.bSb + zh * p.bSh;

    int kEnd = p.K;
    if (p.causal == 2) { int km = m0 + 128; if (km < kEnd) kEnd = km; }
    const int nSlab = kEnd >> 4;

    const int tid  = threadIdx.x;
    const int lane = tid & 31;
    const int warp = tid >> 5;
    const int g    = lane >> 2;
    const int c    = lane & 3;
    const int wm   = warp >> 2;    // 0..1
    const int wn   = warp & 3;     // 0..3

    // producer addressing: thread -> (row, 2 chunks)
    const int prow = tid >> 1;
    const int pq   = (tid & 1) << 1;
    const int swp  = ((prow >> 1) & 1) << 1;
    const unsigned dOff = (unsigned)(prow * 64 + ((pq ^ swp) * 16));
    unsigned smBase = (unsigned)__cvta_generic_to_shared(&sm[0][0][0]);

    const uint32_t* Agp = A + (size_t)(m0 + prow) * p.lda + pq * 4;
    const bool bok = (n0 + prow) < p.N;
    const uint32_t* Bgp = B + (size_t)(bok ? (n0 + prow) : 0) * p.ldb + pq * 4;
    const int bsz = bok ? 16 : 0;

#define ISSUE(SLAB)                                                            \
    do {                                                                       \
        unsigned sb = smBase + (unsigned)(((SLAB) % STAGES) * 16384);          \
        const uint32_t* ag = Agp + (SLAB) * 16;                                \
        const uint32_t* bg = Bgp + (SLAB) * 16;                                \
        cp16(sb + dOff,        ag,     16);                                    \
        cp16(sb + dOff + 16,   ag + 4, 16);                                    \
        cp16(sb + 8192 + dOff,      bg,     bsz);                              \
        cp16(sb + 8192 + dOff + 16, bg + 4, bsz);                              \
    } while (0)

    float acc[4][4][4];
#pragma unroll
    for (int i = 0; i < 4; ++i)
#pragma unroll
        for (int j = 0; j < 4; ++j)
#pragma unroll
            for (int l = 0; l < 4; ++l) acc[i][j][l] = 0.f;

    // prologue: prefetch first STAGES-1 slabs
    {
        int np = nSlab < (STAGES - 1) ? nSlab : (STAGES - 1);
        for (int s = 0; s < np; ++s) { ISSUE(s); cp_commit(); }
        for (int s = np; s < STAGES - 1; ++s) cp_commit();
    }

    for (int it = 0; it < nSlab; ++it) {
        cp_wait1();
        __syncthreads();

        const uint32_t* sa = &sm[it % STAGES][0][0];
        const uint32_t* sb = &sm[it % STAGES][1][0];

        uint32_t Ah[4][4], Al[4][4];
#pragma unroll
        for (int mi = 0; mi < 4; ++mi) {
            const int r = wm * 64 + mi * 16 + g;
            uint2 w0 = ldpair(sa, r,     2 * c);
            uint2 w1 = ldpair(sa, r + 8, 2 * c);
            uint2 w2 = ldpair(sa, r,     2 * c + 8);
            uint2 w3 = ldpair(sa, r + 8, 2 * c + 8);
            Ah[mi][0] = prmt(w0.x, w0.y, PRMT_HI); Al[mi][0] = prmt(w0.x, w0.y, PRMT_LO);
            Ah[mi][1] = prmt(w1.x, w1.y, PRMT_HI); Al[mi][1] = prmt(w1.x, w1.y, PRMT_LO);
            Ah[mi][2] = prmt(w2.x, w2.y, PRMT_HI); Al[mi][2] = prmt(w2.x, w2.y, PRMT_LO);
            Ah[mi][3] = prmt(w3.x, w3.y, PRMT_HI); Al[mi][3] = prmt(w3.x, w3.y, PRMT_LO);
        }
#pragma unroll
        for (int ni = 0; ni < 4; ++ni) {
            const int n = wn * 32 + ni * 8 + g;
            uint2 v0 = ldpair(sb, n, 2 * c);
            uint2 v1 = ldpair(sb, n, 2 * c + 8);
            uint32_t bh0 = prmt(v0.x, v0.y, PRMT_HI), bl0 = prmt(v0.x, v0.y, PRMT_LO);
            uint32_t bh1 = prmt(v1.x, v1.y, PRMT_HI), bl1 = prmt(v1.x, v1.y, PRMT_LO);
#pragma unroll
            for (int mi = 0; mi < 4; ++mi) {
                mma_bf16(acc[mi][ni], Ah[mi][0], Ah[mi][1], Ah[mi][2], Ah[mi][3], bh0, bh1);
                mma_bf16(acc[mi][ni], Ah[mi][0], Ah[mi][1], Ah[mi][2], Ah[mi][3], bl0, bl1);
                mma_bf16(acc[mi][ni], Al[mi][0], Al[mi][1], Al[mi][2], Al[mi][3], bh0, bh1);
            }
        }

        if (it + STAGES - 1 < nSlab) ISSUE(it + STAGES - 1);
        cp_commit();
    }
#undef ISSUE

    // ---- epilogue ----
    if (p.outMode == 0) {
        float* C = (float*)p.C + zb * p.cSb + zh * p.cSh;
#pragma unroll
        for (int mi = 0; mi < 4; ++mi) {
            const int gm = m0 + wm * 64 + mi * 16 + g;
            float* r0 = C + (long long)gm * p.ldc;
            float* r1 = r0 + 8 * p.ldc;
#pragma unroll
            for (int ni = 0; ni < 4; ++ni) {
                const int gn = n0 + wn * 32 + ni * 8 + 2 * c;
                if (gn < p.N) {
                    *(float2*)(r0 + gn) = make_float2(acc[mi][ni][0], acc[mi][ni][1]);
                    *(float2*)(r1 + gn) = make_float2(acc[mi][ni][2], acc[mi][ni][3]);
                }
            }
        }
    } else {
        uint32_t* C = (uint32_t*)p.C + zb * p.cSb + zh * p.cSh;
#pragma unroll
        for (int mi = 0; mi < 4; ++mi) {
            const int gm = m0 + wm * 64 + mi * 16 + g;
            uint32_t* r0 = C + (long long)gm * p.ldc;
            uint32_t* r1 = r0 + 8 * p.ldc;
#pragma unroll
            for (int ni = 0; ni < 4; ++ni) {
                const int gn = n0 + wn * 32 + ni * 8 + 2 * c;
                if (gn < p.N) {
                    *(uint2*)(r0 + gn) = make_uint2(packf(acc[mi][ni][0]), packf(acc[mi][ni][1]));
                    *(uint2*)(r1 + gn) = make_uint2(packf(acc[mi][ni][2]), packf(acc[mi][ni][3]));
                }
            }
        }
    }
}

// ---------------------------- block reduction ------------------------------
__device__ __forceinline__ float blockReduce(float v, bool isMax) {
    __shared__ float sh[32];
    const int lane = threadIdx.x & 31, wid = threadIdx.x >> 5;
    __syncthreads();
#pragma unroll
    for (int o = 16; o > 0; o >>= 1) {
        float t = __shfl_down_sync(0xffffffffu, v, o);
        v = isMax ? fmaxf(v, t) : (v + t);
    }
    if (lane == 0) sh[wid] = v;
    __syncthreads();
    const int nw = blockDim.x >> 5;
    if (wid == 0) {
        v = (lane < nw) ? sh[lane] : (isMax ? -1e30f : 0.f);
#pragma unroll
        for (int o = 16; o > 0; o >>= 1) {
            float t = __shfl_down_sync(0xffffffffu, v, o);
            v = isMax ? fmaxf(v, t) : (v + t);
        }
        if (lane == 0) sh[0] = v;
    }
    __syncthreads();
    return sh[0];
}

// ------------------------------ aux kernels --------------------------------
__global__ void pack_k(const float* __restrict__ in, uint32_t* __restrict__ out, int n) {
    for (int i = blockIdx.x * blockDim.x + threadIdx.x; i < n; i += gridDim.x * blockDim.x)
        out[i] = packf(in[i]);
}

// in fp32 [R][C] -> out packed [C][R]
__global__ void packT_k(const float* __restrict__ in, uint32_t* __restrict__ out,
                        int R, int C) {
    __shared__ float t[32][33];
    const int c0 = blockIdx.x * 32, r0 = blockIdx.y * 32;
#pragma unroll
    for (int i = threadIdx.y; i < 32; i += 8)
        t[i][threadIdx.x] = in[(long long)(r0 + i) * C + c0 + threadIdx.x];
    __syncthreads();
#pragma unroll
    for (int i = threadIdx.y; i < 32; i += 8)
        out[(long long)(c0 + i) * R + r0 + threadIdx.x] = packf(t[threadIdx.x][i]);
}

__global__ void rmsnorm_rows_k(uint32_t* x, const float* __restrict__ w, int n) {
    long long base = (long long)blockIdx.x * n;
    float ss = 0.f;
    for (int i = threadIdx.x; i < n; i += blockDim.x) { float v = upkf(x[base + i]); ss += v * v; }
    ss = blockReduce(ss, false);
    float rn = rsqrtf(ss / (float)n + EPSF);
    for (int i = threadIdx.x; i < n; i += blockDim.x)
        x[base + i] = packf(upkf(x[base + i]) * rn * w[i]);
}

__global__ void kv_process_k(const uint32_t* __restrict__ kv, uint32_t* __restrict__ kext,
                             uint32_t* __restrict__ kextT,
                             const float* __restrict__ w, const float* __restrict__ freqs) {
    const int m = blockIdx.x;
    const int s = m & (SEQ - 1);
    const int b = m >> 11;
    const uint32_t* kr = kv   + (long long)m * KVD;
    uint32_t*       ke = kext + (long long)m * KVD;
    float ss = 0.f;
    for (int i = threadIdx.x; i < KVLR; i += blockDim.x) { float v = upkf(kr[i]); ss += v * v; }
    ss = blockReduce(ss, false);
    float rn = rsqrtf(ss / (float)KVLR + EPSF);
    for (int i = threadIdx.x; i < KVLR; i += blockDim.x) {
        uint32_t pv = packf(upkf(kr[i]) * rn * w[i]);
        ke[i] = pv;
        kextT[(long long)b * KVLR * SEQ + (long long)i * SEQ + s] = pv;
    }
    if (threadIdx.x < 32) {
        const int i = threadIdx.x;
        float th = freqs[s * 32 + i];
        float co, sn; sincosf(th, &sn, &co);
        float x0 = upkf(kr[KVLR + 2 * i]), x1 = upkf(kr[KVLR + 2 * i + 1]);
        ke[KVLR + 2 * i]     = packf(x0 * co - x1 * sn);
        ke[KVLR + 2 * i + 1] = packf(x0 * sn + x1 * co);
    }
}

__global__ void rope_q_k(const uint32_t* __restrict__ q, uint32_t* __restrict__ qext,
                         const float* __restrict__ freqs) {
    const int m = blockIdx.x;
    const int s = m & (SEQ - 1);
    const int h = threadIdx.x >> 5;
    const int i = threadIdx.x & 31;
    float th = freqs[s * 32 + i];
    float co, sn; sincosf(th, &sn, &co);
    const uint32_t* qr = q + (long long)m * QDIM + h * D_QK + D_NOPE;
    uint32_t*       qe = qext + ((long long)m * NH + h) * KVD + KVLR;
    float x0 = upkf(qr[2 * i]), x1 = upkf(qr[2 * i + 1]);
    qe[2 * i]     = packf(x0 * co - x1 * sn);
    qe[2 * i + 1] = packf(x0 * sn + x1 * co);
}

// softmax over fp32 scores row, writes PACKED attn in place (u32 alias).
__global__ void softmax_causal_k(float* scores, float scale) {
    const int s = blockIdx.x;
    long long base = ((long long)blockIdx.y * SEQ + s) * SEQ;
    float* r = scores + base;
    uint32_t* u = (uint32_t*)r;
    const int n = s + 1;
    float mx = -1e30f;
    for (int t = threadIdx.x; t < n; t += blockDim.x) mx = fmaxf(mx, r[t]);
    mx = blockReduce(mx, true);
    float sum = 0.f;
    for (int t = threadIdx.x; t < n; t += blockDim.x) {
        float e = __expf((r[t] - mx) * scale);
        sum += e;
        r[t] = e;
    }
    sum = blockReduce(sum, false);
    float inv = 1.f / sum;
    for (int t = threadIdx.x; t < n; t += blockDim.x) u[t] = packf(r[t] * inv);
    const int bound = ((s >> 7) + 1) << 7;
    for (int t = n + threadIdx.x; t < bound; t += blockDim.x) u[t] = 0u;
}

// ------------------------------- host side ---------------------------------
static void launchGemm(const uint32_t* A, const uint32_t* B, void* C,
                       int M, int N, int K,
                       long long lda, long long ldb, long long ldc,
                       int nb, int nInner,
                       long long aSb, long long aSh,
                       long long bSb, long long bSh,
                       long long cSb, long long cSh,
                       int causal, int outMode) {
    GemmP p;
    p.A = A; p.B = B; p.C = C;
    p.M = M; p.N = N; p.K = K;
    p.lda = lda; p.ldb = ldb; p.ldc = ldc;
    p.aSb = aSb; p.aSh = aSh; p.bSb = bSb; p.bSh = bSh; p.cSb = cSb; p.cSh = cSh;
    p.nInner = nInner; p.causal = causal; p.outMode = outMode;
    dim3 grid((N + 127) / 128, (M + 127) / 128, nb);
    gemm_bf16x3<<<grid, 256>>>(p);
}

extern "C" void kernel_launch(void* const* d_in, const int* in_sizes, int n_in,
                              void* d_out, int out_size) {
    const float* x         = (const float*)d_in[0];
    const float* freqs     = (const float*)d_in[1];
    const float* wq_a      = (const float*)d_in[3];
    const float* q_norm_w  = (const float*)d_in[4];
    const float* wq_b      = (const float*)d_in[5];
    const float* wkv_a     = (const float*)d_in[6];
    const float* kv_norm_w = (const float*)d_in[7];
    const float* wkv_b     = (const float*)d_in[8];
    const float* wo        = (const float*)d_in[9];
    float* out = (float*)d_out;

    uint32_t *xp, *wqaT, *wkvaT, *wqbT, *wkvbP, *wkvbT, *woT;
    uint32_t *qa, *q, *kv, *kext, *kextT, *qext, *olat, *ohead;
    float* scores;
    cudaGetSymbolAddress((void**)&xp,     g_xp);
    cudaGetSymbolAddress((void**)&wqaT,   g_wqaT);
    cudaGetSymbolAddress((void**)&wkvaT,  g_wkvaT);
    cudaGetSymbolAddress((void**)&wqbT,   g_wqbT);
    cudaGetSymbolAddress((void**)&wkvbP,  g_wkvbP);
    cudaGetSymbolAddress((void**)&wkvbT,  g_wkvbT);
    cudaGetSymbolAddress((void**)&woT,    g_woT);
    cudaGetSymbolAddress((void**)&qa,     g_qa);
    cudaGetSymbolAddress((void**)&q,      g_q);
    cudaGetSymbolAddress((void**)&kv,     g_kv);
    cudaGetSymbolAddress((void**)&kext,   g_kext);
    cudaGetSymbolAddress((void**)&kextT,  g_kextT);
    cudaGetSymbolAddress((void**)&qext,   g_qext);
    cudaGetSymbolAddress((void**)&scores, g_scores);
    cudaGetSymbolAddress((void**)&olat,   g_olat);
    cudaGetSymbolAddress((void**)&ohead,  g_ohead);

    const float scale = 1.0f / sqrtf((float)D_QK);

    // ---- pack / transpose-pack inputs ----
    pack_k<<<512, 256>>>(x, xp, MS * DMODEL);
    pack_k<<<256, 256>>>(wkv_b, wkvbP, KVLR * NH * HDIM);
    packT_k<<<dim3(QLR / 32, DMODEL / 32), dim3(32, 8)>>>(wq_a, wqaT, DMODEL, QLR);
    packT_k<<<dim3(KVD / 32, DMODEL / 32), dim3(32, 8)>>>(wkv_a, wkvaT, DMODEL, KVD);
    packT_k<<<dim3(QDIM / 32, QLR / 32), dim3(32, 8)>>>(wq_b, wqbT, QLR, QDIM);
    packT_k<<<dim3((NH * HDIM) / 32, KVLR / 32), dim3(32, 8)>>>(wkv_b, wkvbT, KVLR, NH * HDIM);
    packT_k<<<dim3(DMODEL / 32, DMODEL / 32), dim3(32, 8)>>>(wo, woT, DMODEL, DMODEL);

    // 1. qa = x @ wq_a          (B = wqaT [QLR][DMODEL])
    launchGemm(xp, wqaT, qa, MS, QLR, DMODEL,
               DMODEL, DMODEL, QLR,
               1, 1, 0, 0, 0, 0, 0, 0, 0, 1);
    // 2. kv = x @ wkv_a         (B = wkvaT [576][2048], N=576 OOB-guarded)
    launchGemm(xp, wkvaT, kv, MS, KVD, DMODEL,
               DMODEL, DMODEL, KVD,
               1, 1, 0, 0, 0, 0, 0, 0, 0, 1);
    // 3. rmsnorm(qa) in place (packed)
    rmsnorm_rows_k<<<MS, 256>>>(qa, q_norm_w, QLR);
    // 4. kext (+kextT)
    kv_process_k<<<MS, 256>>>(kv, kext, kextT, kv_norm_w, freqs);
    // 5. q = qa @ wq_b
    launchGemm(qa, wqbT, q, MS, QDIM, QLR,
               QLR, QLR, QDIM,
               1, 1, 0, 0, 0, 0, 0, 0, 0, 1);
    // 6. rope q_pe -> qext[:,512:576]
    rope_q_k<<<MS, NH * 32>>>(q, qext, freqs);
    // 7. qext[:,0:512] = q_nope @ wkv_b_nope^T  (B rows = c, k-contig)
    launchGemm(q, wkvbP, qext, MS, KVLR, D_NOPE,
               QDIM, NH * HDIM, (long long)NH * KVD,
               NH, NH,
               0, D_QK,
               0, HDIM,
               0, KVD, 0, 1);
    // 8. scores = qext @ kext^T  (fp32 out, causal tile skip)
    launchGemm(qext, kext, scores, SEQ, SEQ, KVD,
               (long long)NH * KVD, KVD, SEQ,
               BSZ * NH, NH,
               (long long)SEQ * NH * KVD, KVD,
               (long long)SEQ * KVD, 0,
               (long long)NH * SEQ * SEQ, (long long)SEQ * SEQ,
               1, 0);
    // 9. softmax -> packed attn in place
    softmax_causal_k<<<dim3(SEQ, BSZ * NH), 256>>>(scores, scale);
    // 10. olat = attn @ kv_cache   (B = kextT [b][c][t], causal K-limit)
    launchGemm((const uint32_t*)scores, kextT, olat, SEQ, KVLR, SEQ,
               SEQ, SEQ, KVLR,
               BSZ * NH, NH,
               (long long)NH * SEQ * SEQ, (long long)SEQ * SEQ,
               (long long)KVLR * SEQ, 0,
               (long long)NH * SEQ * KVLR, (long long)SEQ * KVLR,
               2, 1);
    // 11. ohead = olat @ wkv_b_v^T (B = wkvbT rows h*HDIM+128+n, k-contig)
    launchGemm(olat, wkvbT + (long long)D_NOPE * KVLR, ohead, SEQ, D_V, KVLR,
               KVLR, KVLR, DMODEL,
               BSZ * NH, NH,
               (long long)NH * SEQ * KVLR, (long long)SEQ * KVLR,
               0, (long long)HDIM * KVLR,
               (long long)SEQ * DMODEL, D_V,
               0, 1);
    // 12. out = ohead @ wo  (fp32 out)
    launchGemm(ohead, woT, out, MS, DMODEL, DMODEL,
               DMODEL, DMODEL, DMODEL,
               1, 1, 0, 0, 0, 0, 0, 0, 0, 0);
}